// round 6
// baseline (speedup 1.0000x reference)
#include <cuda_runtime.h>
#include <cuda_fp16.h>

// ---------------------------------------------------------------------------
// UnfoldindAndAttention: 8 rounds of normalized graph propagation,
// N=50000, D=64, E=1.6M, attention reweighting after round 4.
// Pull-based CSR (grouped by dst): no float atomics, L2-resident.
// R6: R2's exact mainloop codegen (4-wide unroll, plain loads) + fp16
// attention gather (Yh) + fused rescale + fp16 Xr term.
// ---------------------------------------------------------------------------

#define NMAX 50048
#define EMAX 1600000
#define DV   16          // 64 floats = 16 float4 (or 16 uint2 fp16) per node row

static __device__ int    g_cnt[NMAX];
static __device__ int    g_cursor[NMAX];
static __device__ int    g_rowptr[NMAX + 1];
static __device__ int    g_bsum[256];
static __device__ int    g_boff[256];
static __device__ int    g_col[EMAX];          // src index per CSR slot
static __device__ float  g_w[EMAX];            // attention weight per CSR slot
static __device__ float  g_rs[NMAX];           // (deg+1)^-0.5
static __device__ float4 g_Y[NMAX * DV];       // current Y (fp32)
static __device__ uint2  g_Xr[NMAX * DV];      // 0.5 * rx * X (fp16 x4)
static __device__ uint2  g_YsA[NMAX * DV];     // rs*Y in fp16 ping
static __device__ uint2  g_YsB[NMAX * DV];     // pong
static __device__ uint2  g_Yh[NMAX * DV];      // fp16 copy of Y after step 3

// -------------------------------------------------------------- setup kernels

__global__ void k_zero(int N) {
    int i = blockIdx.x * 256 + threadIdx.x;
    if (i < N) { g_cnt[i] = 0; g_cursor[i] = 0; }
}

__global__ void k_count(const int* __restrict__ dst, int E) {
    int e = blockIdx.x * 256 + threadIdx.x;
    if (e < E) atomicAdd(&g_cnt[dst[e]], 1);
}

// Exclusive block scan (blockDim = 1024). mode 0: cnt -> rowptr (+bsum),
// mode 1: bsum -> boff.
__global__ void k_scan(int mode, int n) {
    const int* in = mode ? g_bsum : g_cnt;
    int* out      = mode ? g_boff : g_rowptr;
    __shared__ int ws[32];
    int g    = blockIdx.x * 1024 + threadIdx.x;
    int lane = threadIdx.x & 31;
    int wid  = threadIdx.x >> 5;
    int v = (g < n) ? in[g] : 0;
    int x = v;
#pragma unroll
    for (int o = 1; o < 32; o <<= 1) {
        int y = __shfl_up_sync(0xFFFFFFFFu, x, o);
        if (lane >= o) x += y;
    }
    if (lane == 31) ws[wid] = x;
    __syncthreads();
    if (wid == 0) {
        int s = ws[lane];
#pragma unroll
        for (int o = 1; o < 32; o <<= 1) {
            int y = __shfl_up_sync(0xFFFFFFFFu, s, o);
            if (lane >= o) s += y;
        }
        ws[lane] = s;
    }
    __syncthreads();
    int boff = wid ? ws[wid - 1] : 0;
    if (g < n) out[g] = boff + x - v;          // exclusive
    if (mode == 0 && threadIdx.x == 0) g_bsum[blockIdx.x] = ws[31];
}

__global__ void k_addoff(int n, int E) {
    int g = blockIdx.x * 1024 + threadIdx.x;
    if (g < n) g_rowptr[g] += g_boff[blockIdx.x];
    if (blockIdx.x == 0 && threadIdx.x == 0) g_rowptr[n] = E;
}

__global__ void k_scatter(const int* __restrict__ src, const int* __restrict__ dst, int E) {
    int e = blockIdx.x * 256 + threadIdx.x;
    if (e < E) {
        int v   = dst[e];
        int off = atomicAdd(&g_cursor[v], 1);
        g_col[g_rowptr[v] + off] = src[e];
    }
}

static __device__ __forceinline__ uint2 pack4(float a, float b, float c, float d) {
    half2 h0 = __floats2half2_rn(a, b);
    half2 h1 = __floats2half2_rn(c, d);
    uint2 r;
    r.x = *(unsigned int*)&h0;
    r.y = *(unsigned int*)&h1;
    return r;
}

static __device__ __forceinline__ float4 unpack4(uint2 q) {
    float2 f0 = __half22float2(*(half2*)&q.x);
    float2 f1 = __half22float2(*(half2*)&q.y);
    return make_float4(f0.x, f0.y, f1.x, f1.y);
}

// Y0 = X; rs/Xr from integer in-degree; YsA = fp16(rs * X)
__global__ void k_init(const float4* __restrict__ X4, int N) {
    int t = blockIdx.x * 256 + threadIdx.x;
    if (t >= N * DV) return;
    int v = t >> 4;
    float deg = (float)g_cnt[v];
    float rs  = 1.0f / sqrtf(deg + 1.0f);
    float hrx = 0.5f / (deg + 1.0f);
    if ((t & 15) == 0) g_rs[v] = rs;
    float4 x = X4[t];
    g_Y[t]   = x;
    g_Xr[t]  = pack4(x.x * hrx, x.y * hrx, x.z * hrx, x.w * hrx);
    g_YsA[t] = pack4(x.x * rs, x.y * rs, x.z * rs, x.w * rs);
}

// -------------------------------------------------------------- propagation

static __device__ __forceinline__ void acc4(float& ax, float& ay, float& az, float& aw,
                                            float w, uint2 q) {
    float2 f0 = __half22float2(*(half2*)&q.x);
    float2 f1 = __half22float2(*(half2*)&q.y);
    ax = fmaf(w, f0.x, ax);
    ay = fmaf(w, f0.y, ay);
    az = fmaf(w, f1.x, az);
    aw = fmaf(w, f1.y, aw);
}

// One propagation step, fused: pull-aggregate + epilogue + next-step operand.
// Half-warp (16 lanes, 4 features each) per node. (R2 codegen: 4-wide unroll,
// plain loads.)
template<bool HAS_W, bool WRITE_YS, bool WRITE_YH, bool TO_OUT>
__global__ void __launch_bounds__(256)
k_agg(float4* __restrict__ outp, int par, int N) {
    int t = blockIdx.x * 256 + threadIdx.x;
    int v = t >> 4;
    if (v >= N) return;
    int l = t & 15;
    const uint2* __restrict__ Yin = par ? g_YsB : g_YsA;
    uint2* Yso                    = par ? g_YsA : g_YsB;

    int s  = g_rowptr[v];
    int se = g_rowptr[v + 1];
    float ax = 0.f, ay = 0.f, az = 0.f, aw = 0.f;

    for (; s + 4 <= se; s += 4) {
        int c0 = g_col[s], c1 = g_col[s + 1], c2 = g_col[s + 2], c3 = g_col[s + 3];
        float w0 = 1.f, w1 = 1.f, w2 = 1.f, w3 = 1.f;
        if (HAS_W) { w0 = g_w[s]; w1 = g_w[s + 1]; w2 = g_w[s + 2]; w3 = g_w[s + 3]; }
        uint2 q0 = Yin[c0 * DV + l];
        uint2 q1 = Yin[c1 * DV + l];
        uint2 q2 = Yin[c2 * DV + l];
        uint2 q3 = Yin[c3 * DV + l];
        acc4(ax, ay, az, aw, w0, q0);
        acc4(ax, ay, az, aw, w1, q1);
        acc4(ax, ay, az, aw, w2, q2);
        acc4(ax, ay, az, aw, w3, q3);
    }
    for (; s < se; ++s) {
        int c    = g_col[s];
        float wv = HAS_W ? g_w[s] : 1.f;
        acc4(ax, ay, az, aw, wv, Yin[c * DV + l]);
    }

    float rs  = g_rs[v];
    float hrs = 0.5f * rs;
    float4 y  = g_Y[t];
    float4 hx = unpack4(g_Xr[t]);
    float4 yn;
    yn.x = 0.5f * y.x + hrs * ax + hx.x;
    yn.y = 0.5f * y.y + hrs * ay + hx.y;
    yn.z = 0.5f * y.z + hrs * az + hx.z;
    yn.w = 0.5f * y.w + hrs * aw + hx.w;

    if (TO_OUT) outp[t] = yn; else g_Y[t] = yn;
    if (WRITE_YS) Yso[t] = pack4(yn.x * rs, yn.y * rs, yn.z * rs, yn.w * rs);
    if (WRITE_YH) g_Yh[t] = pack4(yn.x, yn.y, yn.z, yn.w);
}

// -------------------------------------------------------------- attention

// Per node: Zv from fp32 Y (own row), neighbors gathered from fp16 Yh.
// 16-lane shfl reduction of |dZ|^2; lane 0 computes w and weighted degree.
// Fused rescale: new rs, new Xr = 0.5*rx*X (fp16), YsA = rs_new * Y.
__global__ void __launch_bounds__(256)
k_attn(const float4* __restrict__ X4, const float4* __restrict__ etas4, int N) {
    int t = blockIdx.x * 256 + threadIdx.x;
    int v = t >> 4;
    if (v >= N) return;
    int l = t & 15;
    unsigned mask = 0xFFFFu << (threadIdx.x & 16);

    float4 et = etas4[l];
    float4 yv = g_Y[t];
    float4 zv = make_float4(yv.x * et.x, yv.y * et.y, yv.z * et.z, yv.w * et.w);

    float degw = 0.f;
    int se = g_rowptr[v + 1];
    for (int s = g_rowptr[v]; s < se; ++s) {
        int c     = g_col[s];
        float4 f  = unpack4(g_Yh[c * DV + l]);
        float dx = zv.x - f.x * et.x;
        float dy = zv.y - f.y * et.y;
        float dz = zv.z - f.z * et.z;
        float dw = zv.w - f.w * et.w;
        float p = dx * dx + dy * dy + dz * dz + dw * dw;
        p += __shfl_xor_sync(mask, p, 8);
        p += __shfl_xor_sync(mask, p, 4);
        p += __shfl_xor_sync(mask, p, 2);
        p += __shfl_xor_sync(mask, p, 1);
        if (l == 0) {
            float wv = (p > 2.0f) ? 0.2f : 0.5f / sqrtf(p + 1e-7f);
            g_w[s] = wv;
            degw  += wv;
        }
    }
    // fused rescale: broadcast degw from lane 0 of each 16-lane group
    float deg = __shfl_sync(0xFFFFFFFFu, degw, 0, 16);
    float rs  = 1.0f / sqrtf(deg + 1.0f);
    float hrx = 0.5f / (deg + 1.0f);
    if (l == 0) g_rs[v] = rs;
    float4 x = X4[t];
    g_Xr[t]  = pack4(x.x * hrx, x.y * hrx, x.z * hrx, x.w * hrx);
    g_YsA[t] = pack4(yv.x * rs, yv.y * rs, yv.z * rs, yv.w * rs);
}

// -------------------------------------------------------------- launcher

extern "C" void kernel_launch(void* const* d_in, const int* in_sizes, int n_in,
                              void* d_out, int out_size) {
    const float4* X4    = (const float4*)d_in[0];
    const float4* etas4 = (const float4*)d_in[1];
    const int*    src   = (const int*)d_in[2];
    const int*    dst   = (const int*)d_in[3];
    float4*       out4  = (float4*)d_out;

    int N = in_sizes[0] / 64;
    int E = in_sizes[2];

    int bN  = (N + 255) / 256;
    int bE  = (E + 255) / 256;
    int NB  = (N + 1023) / 1024;
    int bT  = (N * DV + 255) / 256;

    // ---- CSR build ----
    k_zero<<<bN, 256>>>(N);
    k_count<<<bE, 256>>>(dst, E);
    k_scan<<<NB, 1024>>>(0, N);
    k_scan<<<1, 1024>>>(1, NB);
    k_addoff<<<NB, 1024>>>(N, E);
    k_scatter<<<bE, 256>>>(src, dst, E);
    k_init<<<bT, 256>>>(X4, N);

    // ---- steps 0..3: w == 1 (step 3 writes fp16 Y copy for attention) ----
    k_agg<false, true,  false, false><<<bT, 256>>>(out4, 0, N);
    k_agg<false, true,  false, false><<<bT, 256>>>(out4, 1, N);
    k_agg<false, true,  false, false><<<bT, 256>>>(out4, 0, N);
    k_agg<false, false, true,  false><<<bT, 256>>>(out4, 1, N);

    // ---- attention after round 4 (rescale + Xr + YsA fused) ----
    k_attn<<<bT, 256>>>(X4, etas4, N);

    // ---- steps 4..7: attention weights ----
    k_agg<true, true,  false, false><<<bT, 256>>>(out4, 0, N);
    k_agg<true, true,  false, false><<<bT, 256>>>(out4, 1, N);
    k_agg<true, true,  false, false><<<bT, 256>>>(out4, 0, N);
    k_agg<true, false, false, true ><<<bT, 256>>>(out4, 1, N);
}

// round 7
// speedup vs baseline: 1.0438x; 1.0438x over previous
#include <cuda_runtime.h>
#include <cuda_fp16.h>

// ---------------------------------------------------------------------------
// UnfoldindAndAttention: 8 rounds of normalized graph propagation,
// N=50000, D=64, E=1.6M, attention reweighting after round 4.
// Pull-based CSR (grouped by dst): no float atomics, L2-resident.
// R7 = R2 (best known: fp16 agg operand, fp32 attention, plain loads)
//      + fused rescale into k_attn
//      + gather loop unrolled 4 -> 8 (MLP experiment, plain loads).
// ---------------------------------------------------------------------------

#define NMAX 50048
#define EMAX 1600000
#define DV   16          // 64 floats = 16 float4 (or 16 uint2 fp16) per node row

static __device__ int    g_cnt[NMAX];
static __device__ int    g_cursor[NMAX];
static __device__ int    g_rowptr[NMAX + 1];
static __device__ int    g_bsum[256];
static __device__ int    g_boff[256];
static __device__ int    g_col[EMAX];          // src index per CSR slot
static __device__ float  g_w[EMAX];            // attention weight per CSR slot
static __device__ float  g_rs[NMAX];           // (deg+1)^-0.5
static __device__ float  g_rx[NMAX];           // (deg+1)^-1
static __device__ float4 g_Y[NMAX * DV];       // current Y (fp32)
static __device__ uint2  g_YsA[NMAX * DV];     // rs*Y in fp16 ping
static __device__ uint2  g_YsB[NMAX * DV];     // pong

// -------------------------------------------------------------- setup kernels

__global__ void k_zero(int N) {
    int i = blockIdx.x * 256 + threadIdx.x;
    if (i < N) { g_cnt[i] = 0; g_cursor[i] = 0; }
}

__global__ void k_count(const int* __restrict__ dst, int E) {
    int e = blockIdx.x * 256 + threadIdx.x;
    if (e < E) atomicAdd(&g_cnt[dst[e]], 1);
}

// Exclusive block scan (blockDim = 1024). mode 0: cnt -> rowptr (+bsum),
// mode 1: bsum -> boff.
__global__ void k_scan(int mode, int n) {
    const int* in = mode ? g_bsum : g_cnt;
    int* out      = mode ? g_boff : g_rowptr;
    __shared__ int ws[32];
    int g    = blockIdx.x * 1024 + threadIdx.x;
    int lane = threadIdx.x & 31;
    int wid  = threadIdx.x >> 5;
    int v = (g < n) ? in[g] : 0;
    int x = v;
#pragma unroll
    for (int o = 1; o < 32; o <<= 1) {
        int y = __shfl_up_sync(0xFFFFFFFFu, x, o);
        if (lane >= o) x += y;
    }
    if (lane == 31) ws[wid] = x;
    __syncthreads();
    if (wid == 0) {
        int s = ws[lane];
#pragma unroll
        for (int o = 1; o < 32; o <<= 1) {
            int y = __shfl_up_sync(0xFFFFFFFFu, s, o);
            if (lane >= o) s += y;
        }
        ws[lane] = s;
    }
    __syncthreads();
    int boff = wid ? ws[wid - 1] : 0;
    if (g < n) out[g] = boff + x - v;          // exclusive
    if (mode == 0 && threadIdx.x == 0) g_bsum[blockIdx.x] = ws[31];
}

__global__ void k_addoff(int n, int E) {
    int g = blockIdx.x * 1024 + threadIdx.x;
    if (g < n) g_rowptr[g] += g_boff[blockIdx.x];
    if (blockIdx.x == 0 && threadIdx.x == 0) g_rowptr[n] = E;
}

__global__ void k_scatter(const int* __restrict__ src, const int* __restrict__ dst, int E) {
    int e = blockIdx.x * 256 + threadIdx.x;
    if (e < E) {
        int v   = dst[e];
        int off = atomicAdd(&g_cursor[v], 1);
        g_col[g_rowptr[v] + off] = src[e];
    }
}

static __device__ __forceinline__ uint2 pack4(float a, float b, float c, float d) {
    half2 h0 = __floats2half2_rn(a, b);
    half2 h1 = __floats2half2_rn(c, d);
    uint2 r;
    r.x = *(unsigned int*)&h0;
    r.y = *(unsigned int*)&h1;
    return r;
}

// Y0 = X; rs/rx from integer in-degree; YsA = fp16(rs * X)
__global__ void k_init(const float4* __restrict__ X4, int N) {
    int t = blockIdx.x * 256 + threadIdx.x;
    if (t >= N * DV) return;
    int v = t >> 4;
    float deg = (float)g_cnt[v];
    float rs  = 1.0f / sqrtf(deg + 1.0f);
    if ((t & 15) == 0) { g_rs[v] = rs; g_rx[v] = 1.0f / (deg + 1.0f); }
    float4 x = X4[t];
    g_Y[t]   = x;
    g_YsA[t] = pack4(x.x * rs, x.y * rs, x.z * rs, x.w * rs);
}

// -------------------------------------------------------------- propagation

static __device__ __forceinline__ void acc4(float& ax, float& ay, float& az, float& aw,
                                            float w, uint2 q) {
    float2 f0 = __half22float2(*(half2*)&q.x);
    float2 f1 = __half22float2(*(half2*)&q.y);
    ax = fmaf(w, f0.x, ax);
    ay = fmaf(w, f0.y, ay);
    az = fmaf(w, f1.x, az);
    aw = fmaf(w, f1.y, aw);
}

// One propagation step, fused: pull-aggregate + epilogue + next-step operand.
// Half-warp (16 lanes, 4 features each) per node. 8 gathers in flight.
template<bool HAS_W, bool WRITE_YS, bool TO_OUT>
__global__ void __launch_bounds__(256)
k_agg(const float4* __restrict__ X4, float4* __restrict__ outp, int par, int N) {
    int t = blockIdx.x * 256 + threadIdx.x;
    int v = t >> 4;
    if (v >= N) return;
    int l = t & 15;
    const uint2* __restrict__ Yin = par ? g_YsB : g_YsA;
    uint2* Yso                    = par ? g_YsA : g_YsB;

    int s  = g_rowptr[v];
    int se = g_rowptr[v + 1];
    float ax = 0.f, ay = 0.f, az = 0.f, aw = 0.f;

    for (; s + 8 <= se; s += 8) {
        int c0 = g_col[s],     c1 = g_col[s + 1], c2 = g_col[s + 2], c3 = g_col[s + 3];
        int c4 = g_col[s + 4], c5 = g_col[s + 5], c6 = g_col[s + 6], c7 = g_col[s + 7];
        float w0 = 1.f, w1 = 1.f, w2 = 1.f, w3 = 1.f;
        float w4 = 1.f, w5 = 1.f, w6 = 1.f, w7 = 1.f;
        if (HAS_W) {
            w0 = g_w[s];     w1 = g_w[s + 1]; w2 = g_w[s + 2]; w3 = g_w[s + 3];
            w4 = g_w[s + 4]; w5 = g_w[s + 5]; w6 = g_w[s + 6]; w7 = g_w[s + 7];
        }
        uint2 q0 = Yin[c0 * DV + l];
        uint2 q1 = Yin[c1 * DV + l];
        uint2 q2 = Yin[c2 * DV + l];
        uint2 q3 = Yin[c3 * DV + l];
        uint2 q4 = Yin[c4 * DV + l];
        uint2 q5 = Yin[c5 * DV + l];
        uint2 q6 = Yin[c6 * DV + l];
        uint2 q7 = Yin[c7 * DV + l];
        acc4(ax, ay, az, aw, w0, q0);
        acc4(ax, ay, az, aw, w1, q1);
        acc4(ax, ay, az, aw, w2, q2);
        acc4(ax, ay, az, aw, w3, q3);
        acc4(ax, ay, az, aw, w4, q4);
        acc4(ax, ay, az, aw, w5, q5);
        acc4(ax, ay, az, aw, w6, q6);
        acc4(ax, ay, az, aw, w7, q7);
    }
    for (; s < se; ++s) {
        int c    = g_col[s];
        float wv = HAS_W ? g_w[s] : 1.f;
        acc4(ax, ay, az, aw, wv, Yin[c * DV + l]);
    }

    float rs  = g_rs[v];
    float rx  = g_rx[v];
    float hrs = 0.5f * rs;
    float hrx = 0.5f * rx;
    float4 y = g_Y[t];
    float4 x = X4[t];
    float4 yn;
    yn.x = 0.5f * y.x + hrs * ax + hrx * x.x;
    yn.y = 0.5f * y.y + hrs * ay + hrx * x.y;
    yn.z = 0.5f * y.z + hrs * az + hrx * x.z;
    yn.w = 0.5f * y.w + hrs * aw + hrx * x.w;

    if (TO_OUT) outp[t] = yn; else g_Y[t] = yn;
    if (WRITE_YS) Yso[t] = pack4(yn.x * rs, yn.y * rs, yn.z * rs, yn.w * rs);
}

// -------------------------------------------------------------- attention

// Per node: Zv in registers, gather Y[src] (fp32), 16-lane shfl reduction of
// |dZ|^2. Lane 0 computes w and weighted degree. Fused rescale: new rs/rx
// and YsA = rs_new * Y (operand for step 4).
__global__ void __launch_bounds__(256)
k_attn(const float4* __restrict__ etas4, int N) {
    int t = blockIdx.x * 256 + threadIdx.x;
    int v = t >> 4;
    if (v >= N) return;
    int l = t & 15;
    unsigned mask = 0xFFFFu << (threadIdx.x & 16);

    float4 et = etas4[l];
    float4 yv = g_Y[t];
    float4 zv = make_float4(yv.x * et.x, yv.y * et.y, yv.z * et.z, yv.w * et.w);

    float degw = 0.f;
    int se = g_rowptr[v + 1];
    for (int s = g_rowptr[v]; s < se; ++s) {
        int c     = g_col[s];
        float4 yc = g_Y[c * DV + l];
        float dx = zv.x - yc.x * et.x;
        float dy = zv.y - yc.y * et.y;
        float dz = zv.z - yc.z * et.z;
        float dw = zv.w - yc.w * et.w;
        float p = dx * dx + dy * dy + dz * dz + dw * dw;
        p += __shfl_xor_sync(mask, p, 8);
        p += __shfl_xor_sync(mask, p, 4);
        p += __shfl_xor_sync(mask, p, 2);
        p += __shfl_xor_sync(mask, p, 1);
        if (l == 0) {
            float wv = (p > 2.0f) ? 0.2f : 0.5f / sqrtf(p + 1e-7f);
            g_w[s] = wv;
            degw  += wv;
        }
    }
    // fused rescale: broadcast degw from lane 0 of each 16-lane group
    float deg = __shfl_sync(0xFFFFFFFFu, degw, 0, 16);
    float rs  = 1.0f / sqrtf(deg + 1.0f);
    if (l == 0) { g_rs[v] = rs; g_rx[v] = 1.0f / (deg + 1.0f); }
    g_YsA[t] = pack4(yv.x * rs, yv.y * rs, yv.z * rs, yv.w * rs);
}

// -------------------------------------------------------------- launcher

extern "C" void kernel_launch(void* const* d_in, const int* in_sizes, int n_in,
                              void* d_out, int out_size) {
    const float4* X4    = (const float4*)d_in[0];
    const float4* etas4 = (const float4*)d_in[1];
    const int*    src   = (const int*)d_in[2];
    const int*    dst   = (const int*)d_in[3];
    float4*       out4  = (float4*)d_out;

    int N = in_sizes[0] / 64;
    int E = in_sizes[2];

    int bN  = (N + 255) / 256;
    int bE  = (E + 255) / 256;
    int NB  = (N + 1023) / 1024;
    int bT  = (N * DV + 255) / 256;

    // ---- CSR build ----
    k_zero<<<bN, 256>>>(N);
    k_count<<<bE, 256>>>(dst, E);
    k_scan<<<NB, 1024>>>(0, N);
    k_scan<<<1, 1024>>>(1, NB);
    k_addoff<<<NB, 1024>>>(N, E);
    k_scatter<<<bE, 256>>>(src, dst, E);
    k_init<<<bT, 256>>>(X4, N);

    // ---- steps 0..3: w == 1 ----
    k_agg<false, true,  false><<<bT, 256>>>(X4, out4, 0, N);
    k_agg<false, true,  false><<<bT, 256>>>(X4, out4, 1, N);
    k_agg<false, true,  false><<<bT, 256>>>(X4, out4, 0, N);
    k_agg<false, false, false><<<bT, 256>>>(X4, out4, 1, N);

    // ---- attention after round 4 (rescale fused) ----
    k_attn<<<bT, 256>>>(etas4, N);

    // ---- steps 4..7: attention weights ----
    k_agg<true, true,  false><<<bT, 256>>>(X4, out4, 0, N);
    k_agg<true, true,  false><<<bT, 256>>>(X4, out4, 1, N);
    k_agg<true, true,  false><<<bT, 256>>>(X4, out4, 0, N);
    k_agg<true, false, true ><<<bT, 256>>>(X4, out4, 1, N);
}